// round 12
// baseline (speedup 1.0000x reference)
#include <cuda_runtime.h>
#include <cstdint>

#define B_  4
#define HC_ 32
#define WC_ 32
#define KC_ 1024
#define HF_ 128
#define WF_ 128
#define KF_ 256
#define DC_ 4

__device__ float g_anorm[B_ * HC_ * WC_];
__device__ float g_fnorm[B_ * HF_ * WF_];
__device__ int   g_cm[B_ * HC_ * WC_ * 2];
__device__ float g_pv[B_ * HC_ * WC_ * 4];   // [q][split]
__device__ int   g_pi[B_ * HC_ * WC_ * 4];

union F2U { unsigned long long u; float2 f; };

__device__ __forceinline__ void ffma2(unsigned long long &d,
                                      unsigned long long a,
                                      unsigned long long b) {
    asm("fma.rn.f32x2 %0, %1, %2, %0;" : "+l"(d) : "l"(a), "l"(b));
}
__device__ __forceinline__ unsigned long long dup2(float x) {
    unsigned long long r;
    asm("mov.b64 %0, {%1, %1};" : "=l"(r) : "f"(x));
    return r;
}

// ---------------------------------------------------------------------------
// Kernel 1: candidate squared norms (one warp per row). DRAM-roofline bound.
// ---------------------------------------------------------------------------
__global__ void norms_kernel(const float* __restrict__ g1c,
                             const float* __restrict__ g1f) {
    int w    = (blockIdx.x * blockDim.x + threadIdx.x) >> 5;
    int lane = threadIdx.x & 31;
    float s = 0.f;
    if (w < B_ * HC_ * WC_) {
        const float* p = g1c + (size_t)w * KC_;
#pragma unroll
        for (int i = 0; i < KC_ / 32; i++) { float v = p[lane + i * 32]; s += v * v; }
#pragma unroll
        for (int o = 16; o; o >>= 1) s += __shfl_xor_sync(0xFFFFFFFFu, s, o);
        if (lane == 0) g_anorm[w] = s;
    } else if (w < B_ * HC_ * WC_ + B_ * HF_ * WF_) {
        int r = w - B_ * HC_ * WC_;
        const float* p = g1f + (size_t)r * KF_;
#pragma unroll
        for (int i = 0; i < KF_ / 32; i++) { float v = p[lane + i * 32]; s += v * v; }
#pragma unroll
        for (int o = 16; o; o >>= 1) s += __shfl_xor_sync(0xFFFFFFFFu, s, o);
        if (lane == 0) g_fnorm[r] = s;
    }
}

// ---------------------------------------------------------------------------
// Kernel 2: coarse match. Grid (32 qblk, 4 batch, 4 csplit) = 512 blocks,
// 128 thr, ~4 blocks/SM -> one wave. Block: 32 q x 256 cands.
// Warp w owns queries w*8..+7 (f32x2-dup broadcast); lane l owns cands
// {l*4..+3} U {128+l*4..+3} (phase-aligned conflict-free LDS.128 pairs).
// 8q x 8c = 64 MAC/thread/k as 32 FFMA2. BK=8 double-buffered, reg prefetch,
// one sync per chunk. Warp-local shfl argmin (lane 0 writes 8 partials).
// score = |a|^2 - 2 q.a
// ---------------------------------------------------------------------------
__global__ __launch_bounds__(128, 4)
void coarse_kernel(const float* __restrict__ A,
                   const float* __restrict__ Q) {
    const int b   = blockIdx.y;
    const int q0  = blockIdx.x * 32;
    const int cs  = blockIdx.z;
    const int S   = cs * 256;
    const int tid = threadIdx.x;
    const int w   = tid >> 5;
    const int l   = tid & 31;

    __shared__ float q_s[2][8][32];                    // 2 KB
    __shared__ __align__(16) float c_s[2][8][256];     // 16 KB

    const float* Ab = A + (size_t)b * (HC_ * WC_) * KC_;
    const float* Qb = Q + (size_t)b * (HC_ * WC_) * KC_;

    const float* c0src = Ab + (size_t)(S + tid) * KC_;
    const float* c1src = Ab + (size_t)(S + 128 + tid) * KC_;
    const int qp = tid >> 2;              // 0..31
    const int qk = (tid & 3) * 2;         // 0,2,4,6
    const float* qsrc = Qb + (size_t)(q0 + qp) * KC_ + qk;

    float4 ra0 = *(const float4*)(c0src);
    float4 ra1 = *(const float4*)(c0src + 4);
    float4 ra2 = *(const float4*)(c1src);
    float4 ra3 = *(const float4*)(c1src + 4);
    float2 rq  = *(const float2*)(qsrc);

    unsigned long long acc[8][4];
#pragma unroll
    for (int r = 0; r < 8; r++)
#pragma unroll
        for (int p = 0; p < 4; p++) acc[r][p] = 0ULL;

    for (int ck = 0; ck < 128; ck++) {
        const int bw = ck & 1;
        c_s[bw][0][tid] = ra0.x; c_s[bw][1][tid] = ra0.y;
        c_s[bw][2][tid] = ra0.z; c_s[bw][3][tid] = ra0.w;
        c_s[bw][4][tid] = ra1.x; c_s[bw][5][tid] = ra1.y;
        c_s[bw][6][tid] = ra1.z; c_s[bw][7][tid] = ra1.w;
        c_s[bw][0][tid + 128] = ra2.x; c_s[bw][1][tid + 128] = ra2.y;
        c_s[bw][2][tid + 128] = ra2.z; c_s[bw][3][tid + 128] = ra2.w;
        c_s[bw][4][tid + 128] = ra3.x; c_s[bw][5][tid + 128] = ra3.y;
        c_s[bw][6][tid + 128] = ra3.z; c_s[bw][7][tid + 128] = ra3.w;
        q_s[bw][qk][qp]     = rq.x;
        q_s[bw][qk + 1][qp] = rq.y;
        if (ck + 1 < 128) {
            const int k0 = (ck + 1) * 8;
            ra0 = *(const float4*)(c0src + k0);
            ra1 = *(const float4*)(c0src + k0 + 4);
            ra2 = *(const float4*)(c1src + k0);
            ra3 = *(const float4*)(c1src + k0 + 4);
            rq  = *(const float2*)(qsrc + k0);
        }
        __syncthreads();
#pragma unroll
        for (int k = 0; k < 8; k++) {
            float4 qa = *(const float4*)&q_s[bw][k][w * 8];
            float4 qb = *(const float4*)&q_s[bw][k][w * 8 + 4];
            ulonglong2 ca = *(const ulonglong2*)&c_s[bw][k][l * 4];
            ulonglong2 cb = *(const ulonglong2*)&c_s[bw][k][128 + l * 4];
            float qs[8] = { qa.x, qa.y, qa.z, qa.w, qb.x, qb.y, qb.z, qb.w };
#pragma unroll
            for (int r = 0; r < 8; r++) {
                unsigned long long qd = dup2(qs[r]);
                ffma2(acc[r][0], qd, ca.x);
                ffma2(acc[r][1], qd, ca.y);
                ffma2(acc[r][2], qd, cb.x);
                ffma2(acc[r][3], qd, cb.y);
            }
        }
    }

    // epilogue: per-lane argmin over its 8 cands, full-warp shfl reduce.
    const float* anb = g_anorm + b * (HC_ * WC_);
#pragma unroll
    for (int r = 0; r < 8; r++) {
        float bv = 3.402823466e38f; int bi = 0;
#pragma unroll
        for (int p = 0; p < 4; p++) {
            F2U u; u.u = acc[r][p];
            int c0 = (p < 2) ? (l * 4 + p * 2) : (128 + l * 4 + (p - 2) * 2);
            int g0 = S + c0;
            float s0 = anb[g0] - 2.f * u.f.x;
            float s1 = anb[g0 + 1] - 2.f * u.f.y;
            if (s0 < bv || (s0 == bv && g0 < bi))     { bv = s0; bi = g0; }
            if (s1 < bv || (s1 == bv && g0 + 1 < bi)) { bv = s1; bi = g0 + 1; }
        }
#pragma unroll
        for (int off = 16; off; off >>= 1) {
            float ov = __shfl_xor_sync(0xFFFFFFFFu, bv, off);
            int   oi = __shfl_xor_sync(0xFFFFFFFFu, bi, off);
            if (ov < bv || (ov == bv && oi < bi)) { bv = ov; bi = oi; }
        }
        if (l == 0) {
            int q = b * (HC_ * WC_) + q0 + w * 8 + r;
            g_pv[q * 4 + cs] = bv;
            g_pi[q * 4 + cs] = bi;
        }
    }
}

// ---------------------------------------------------------------------------
// Kernel 2b: merge 4 ordered split partials per query (explicit idx tie ->
// jnp.argmin first-min preserved).
// ---------------------------------------------------------------------------
__global__ void merge_kernel(float* __restrict__ out) {
    int q = blockIdx.x * blockDim.x + threadIdx.x;
    if (q >= B_ * HC_ * WC_) return;
    float bv = g_pv[q * 4]; int bi = g_pi[q * 4];
#pragma unroll
    for (int s = 1; s < 4; s++) {
        float v = g_pv[q * 4 + s]; int i2 = g_pi[q * 4 + s];
        if (v < bv || (v == bv && i2 < bi)) { bv = v; bi = i2; }
    }
    int ro = bi >> 5, co = bi & 31;
    out[q * 2 + 0] = (float)ro;
    out[q * 2 + 1] = (float)co;
    g_cm[q * 2 + 0] = ro;
    g_cm[q * 2 + 1] = co;
}

// ---------------------------------------------------------------------------
// Kernel 3: fine match. Block = 4 cells (ci, cj4*4+cell), 160 thr, compute
// tid<144: cell=tid/36, t=tid%36, qg=t&1 (queries qg*8..+7), sg=t>>1
// (slots {sg*4..+3} U {72+sg*4..+3}). 8q x 8s = 32 FFMA2/thread/k.
// Lane pairs share addresses -> broadcast dedup; phase-aligned LDS.128.
// chunk=16k, 2 syncs/chunk. Reductions aliased into c buffer.
// Duplicated candidates bitwise-equal -> smallest-slot tie-break ==
// jnp.argmin first-min.
// ---------------------------------------------------------------------------
__global__ __launch_bounds__(160, 4)
void fine_kernel(const float* __restrict__ F1,
                 const float* __restrict__ FK,
                 float* __restrict__ out) {
    const int b   = blockIdx.z;
    const int ci  = blockIdx.y;
    const int cj4 = blockIdx.x;
    const int tid = threadIdx.x;

    // raw: [0,37888) c_f[16][4][148]; [37888,41984) q_f[16][4][16]
    // after compute: red_v[4][16][20] at 0, red_i[4][16][20] at 8192.
    __shared__ __align__(16) unsigned char raw[37888 + 4096];
    typedef float CF[4][148];
    typedef float QF[4][16];
    CF* c_f = reinterpret_cast<CF*>(raw);                 // [16]
    QF* q_f = reinterpret_cast<QF*>(raw + 37888);         // [16]
    float (*red_v)[16][20] = reinterpret_cast<float (*)[16][20]>(raw);
    int   (*red_i)[16][20] = reinterpret_cast<int   (*)[16][20]>(raw + 8192);
    __shared__ int nbr_r[4][9], nbr_c[4][9];

    if (tid < 36) {
        int cl = tid / 9, nb = tid % 9;
        int di = nb / 3 - 1, dj = nb % 3 - 1;
        int cjv = cj4 * 4 + cl;
        int ii = min(max(ci + di, 0), HC_ - 1);
        int jj = min(max(cjv + dj, 0), WC_ - 1);
        const int* p = g_cm + ((b * HC_ + ii) * WC_ + jj) * 2;
        nbr_r[cl][nb] = min(max(p[0], 0), HC_ - 1);
        nbr_c[cl][nb] = min(max(p[1], 0), WC_ - 1);
    }

    const float* F1b = F1 + (size_t)b * HF_ * WF_ * KF_;
    const float* fnb = g_fnorm + b * HF_ * WF_;

    const int ctid = (tid < 144) ? tid : 0;
    const int cell = ctid / 36;
    const int t36  = ctid % 36;
    const int qg   = t36 & 1;
    const int sg   = t36 >> 1;

    unsigned long long acc[8][4];
#pragma unroll
    for (int r = 0; r < 8; r++)
#pragma unroll
        for (int p = 0; p < 4; p++) acc[r][p] = 0ULL;

    for (int ksub = 0; ksub < 16; ksub++) {
        __syncthreads();   // first iter: nbr ready; later: compute done
        // stage c: 576 rows x 16 k (4 float4 quarters)
        for (int i = tid; i < 2304; i += 160) {
            int qtr = i / 576, row = i - qtr * 576;
            int cl = row / 144, sl = row - cl * 144;
            int n = sl >> 4, pp = sl & 15;
            int rr = nbr_r[cl][n] * DC_ + (pp >> 2);
            int cc = nbr_c[cl][n] * DC_ + (pp & 3);
            float4 v = *(const float4*)(F1b + (size_t)(rr * WF_ + cc) * KF_
                                        + ksub * 16 + qtr * 4);
            c_f[qtr * 4 + 0][cl][sl] = v.x;
            c_f[qtr * 4 + 1][cl][sl] = v.y;
            c_f[qtr * 4 + 2][cl][sl] = v.z;
            c_f[qtr * 4 + 3][cl][sl] = v.w;
        }
        // stage q: 4 cells x 16 q x 16 k
        for (int i = tid; i < 256; i += 160) {
            int cl = i >> 6, qp = (i >> 2) & 15, qtr = i & 3;
            int R = ci * DC_ + (qp >> 2);
            int C = (cj4 * 4 + cl) * DC_ + (qp & 3);
            float4 v = *(const float4*)(FK + ((size_t)(b * HF_ + R) * WF_ + C) * KF_
                                        + ksub * 16 + qtr * 4);
            q_f[qtr * 4 + 0][cl][qp] = v.x;
            q_f[qtr * 4 + 1][cl][qp] = v.y;
            q_f[qtr * 4 + 2][cl][qp] = v.z;
            q_f[qtr * 4 + 3][cl][qp] = v.w;
        }
        __syncthreads();
        if (tid < 144) {
#pragma unroll
            for (int k = 0; k < 16; k++) {
                float4 qa = *(const float4*)&q_f[k][cell][qg * 8];
                float4 qb = *(const float4*)&q_f[k][cell][qg * 8 + 4];
                ulonglong2 ca = *(const ulonglong2*)&c_f[k][cell][sg * 4];
                ulonglong2 cb = *(const ulonglong2*)&c_f[k][cell][72 + sg * 4];
                float qs[8] = { qa.x, qa.y, qa.z, qa.w, qb.x, qb.y, qb.z, qb.w };
#pragma unroll
                for (int r = 0; r < 8; r++) {
                    unsigned long long qd = dup2(qs[r]);
                    ffma2(acc[r][0], qd, ca.x);
                    ffma2(acc[r][1], qd, ca.y);
                    ffma2(acc[r][2], qd, cb.x);
                    ffma2(acc[r][3], qd, cb.y);
                }
            }
        }
    }

    __syncthreads();   // all compute done; c buffer reusable for reductions
    if (tid < 144) {
        // norms for this thread's 8 slots
        float fn[8];
#pragma unroll
        for (int j = 0; j < 8; j++) {
            int slot = (j < 4) ? (sg * 4 + j) : (72 + sg * 4 + (j - 4));
            int n = slot >> 4, pp = slot & 15;
            int rr = nbr_r[cell][n] * DC_ + (pp >> 2);
            int cc = nbr_c[cell][n] * DC_ + (pp & 3);
            fn[j] = fnb[rr * WF_ + cc];
        }
#pragma unroll
        for (int r = 0; r < 8; r++) {
            float bv = 3.402823466e38f; int bi = 0;
#pragma unroll
            for (int p = 0; p < 4; p++) {
                F2U u; u.u = acc[r][p];
                int s0 = (p < 2) ? (sg * 4 + p * 2) : (72 + sg * 4 + (p - 2) * 2);
                int j0 = (p < 2) ? (p * 2) : (4 + (p - 2) * 2);
                float sc0 = fn[j0]     - 2.f * u.f.x;
                float sc1 = fn[j0 + 1] - 2.f * u.f.y;
                if (sc0 < bv || (sc0 == bv && s0 < bi))     { bv = sc0; bi = s0; }
                if (sc1 < bv || (sc1 == bv && s0 + 1 < bi)) { bv = sc1; bi = s0 + 1; }
            }
            red_v[cell][qg * 8 + r][sg] = bv;
            red_i[cell][qg * 8 + r][sg] = bi;
        }
    }
    __syncthreads();
    if (tid < 64) {
        int cl = tid >> 4, q = tid & 15;
        float bv = red_v[cl][q][0]; int bi = red_i[cl][q][0];
        for (int t = 1; t < 18; t++) {
            float v = red_v[cl][q][t]; int i2 = red_i[cl][q][t];
            if (v < bv || (v == bv && i2 < bi)) { bv = v; bi = i2; }
        }
        int n = bi >> 4, pp = bi & 15;
        int rr = nbr_r[cl][n] * DC_ + (pp >> 2);
        int cc = nbr_c[cl][n] * DC_ + (pp & 3);
        int R = ci * DC_ + (q >> 2);
        int C = (cj4 * 4 + cl) * DC_ + (q & 3);
        float* o = out + ((size_t)(b * HF_ + R) * WF_ + C) * 2;
        o[0] = (float)rr; o[1] = (float)cc;
    }
}

// ---------------------------------------------------------------------------
extern "C" void kernel_launch(void* const* d_in, const int* in_sizes, int n_in,
                              void* d_out, int out_size) {
    int idx[16];
    int m = n_in < 16 ? n_in : 16;
    for (int i = 0; i < m; i++) idx[i] = i;
    for (int i = 1; i < m; i++) {
        int key = idx[i];
        long long ks = in_sizes[key];
        int j = i - 1;
        while (j >= 0 && (long long)in_sizes[idx[j]] > ks) {
            idx[j + 1] = idx[j]; j--;
        }
        idx[j + 1] = key;
    }
    if (m < 4) return;
    const float* g1c = (const float*)d_in[idx[0]];      // F_g1_coarse
    const float* gkc = (const float*)d_in[idx[1]];      // F_gk_coarse
    const float* g1f = (const float*)d_in[idx[m - 2]];  // F_g1_fine
    const float* gkf = (const float*)d_in[idx[m - 1]];  // F_gk_fine
    float* out = (float*)d_out;

    norms_kernel<<<(B_ * HC_ * WC_ + B_ * HF_ * WF_) / 8, 256>>>(g1c, g1f);

    dim3 gc(HC_ * WC_ / 32, B_, 4);
    coarse_kernel<<<gc, 128>>>(g1c, gkc);

    merge_kernel<<<(B_ * HC_ * WC_ + 255) / 256, 256>>>(out);

    dim3 gf(WC_ / 4, HC_, B_);
    fine_kernel<<<gf, 160>>>(g1f, gkf, out + B_ * HC_ * WC_ * 2);
}

// round 14
// speedup vs baseline: 1.0558x; 1.0558x over previous
#include <cuda_runtime.h>
#include <cstdint>

#define B_  4
#define HC_ 32
#define WC_ 32
#define KC_ 1024
#define HF_ 128
#define WF_ 128
#define KF_ 256
#define DC_ 4

__device__ float g_anorm[B_ * HC_ * WC_];
__device__ float g_fnorm[B_ * HF_ * WF_];
__device__ int   g_cm[B_ * HC_ * WC_ * 2];
__device__ float g_pv[B_ * 1024 * 8];     // [q][ctile]
__device__ int   g_pi[B_ * 1024 * 8];
// 3xTF32 splits (stored as fp32 bit-exact tf32 values): [b][row][k]
__device__ float g_qb[(size_t)B_ * 1024 * 1024];
__device__ float g_qs2[(size_t)B_ * 1024 * 1024];
__device__ float g_cb[(size_t)B_ * 1024 * 1024];
__device__ float g_cs2[(size_t)B_ * 1024 * 1024];

union F2U { unsigned long long u; float2 f; };

__device__ __forceinline__ void ffma2(unsigned long long &d,
                                      unsigned long long a,
                                      unsigned long long b) {
    asm("fma.rn.f32x2 %0, %1, %2, %0;" : "+l"(d) : "l"(a), "l"(b));
}
__device__ __forceinline__ unsigned long long dup2(float x) {
    unsigned long long r;
    asm("mov.b64 %0, {%1, %1};" : "=l"(r) : "f"(x));
    return r;
}
__device__ __forceinline__ uint32_t tf32_of(float x) {
    uint32_t r;
    asm("cvt.rna.tf32.f32 %0, %1;" : "=r"(r) : "f"(x));
    return r;
}
__device__ __forceinline__ void mma_tf32(float* d, const uint32_t* a,
                                         const uint32_t* b) {
    asm volatile(
        "mma.sync.aligned.m16n8k8.row.col.f32.tf32.tf32.f32 "
        "{%0,%1,%2,%3}, {%4,%5,%6,%7}, {%8,%9}, {%0,%1,%2,%3};"
        : "+f"(d[0]), "+f"(d[1]), "+f"(d[2]), "+f"(d[3])
        : "r"(a[0]), "r"(a[1]), "r"(a[2]), "r"(a[3]), "r"(b[0]), "r"(b[1]));
}

// ---------------------------------------------------------------------------
// Kernel 1: candidate squared norms (one warp per row). DRAM-roofline bound.
// ---------------------------------------------------------------------------
__global__ void norms_kernel(const float* __restrict__ g1c,
                             const float* __restrict__ g1f) {
    int w    = (blockIdx.x * blockDim.x + threadIdx.x) >> 5;
    int lane = threadIdx.x & 31;
    float s = 0.f;
    if (w < B_ * HC_ * WC_) {
        const float* p = g1c + (size_t)w * KC_;
#pragma unroll
        for (int i = 0; i < KC_ / 32; i++) { float v = p[lane + i * 32]; s += v * v; }
#pragma unroll
        for (int o = 16; o; o >>= 1) s += __shfl_xor_sync(0xFFFFFFFFu, s, o);
        if (lane == 0) g_anorm[w] = s;
    } else if (w < B_ * HC_ * WC_ + B_ * HF_ * WF_) {
        int r = w - B_ * HC_ * WC_;
        const float* p = g1f + (size_t)r * KF_;
#pragma unroll
        for (int i = 0; i < KF_ / 32; i++) { float v = p[lane + i * 32]; s += v * v; }
#pragma unroll
        for (int o = 16; o; o >>= 1) s += __shfl_xor_sync(0xFFFFFFFFu, s, o);
        if (lane == 0) g_fnorm[r] = s;
    }
}

// ---------------------------------------------------------------------------
// Kernel 1b: 3xTF32 split of coarse tensors. One warp per row (8192 rows).
// big = tf32(x); small = tf32(x - big).
// ---------------------------------------------------------------------------
__global__ void convert_kernel(const float* __restrict__ g1c,
                               const float* __restrict__ gkc) {
    int row  = blockIdx.x * 8 + (threadIdx.x >> 5);
    int lane = threadIdx.x & 31;
    int r = row & 4095;
    const float* src = (row < 4096 ? g1c : gkc) + (size_t)r * 1024;
    float* db = (row < 4096 ? g_cb : g_qb)  + (size_t)r * 1024;
    float* ds = (row < 4096 ? g_cs2 : g_qs2) + (size_t)r * 1024;
    for (int i = lane; i < 1024; i += 32) {
        float x = src[i];
        uint32_t bb = tf32_of(x);
        float bf = __uint_as_float(bb);
        uint32_t sb = tf32_of(x - bf);
        db[i] = bf;
        ds[i] = __uint_as_float(sb);
    }
}

// ---------------------------------------------------------------------------
// Kernel 2: coarse match on mma.sync (tf32, 3xTF32). Grid (16 qt, 8 ct, 4 b).
// Block 256 thr = 2(M) x 4(N) warps; tile 64 q x 128 c; warp 32x32.
// Per 32-k chunk: stage A/B splits into FRAGMENT-MAJOR smem (A-frag = one
// LDS.128, B-frag = one LDS.64, conflict-free); 3 products (bb, bs, sb) x
// 4 k8 x 8 mma per warp. Epilogue: per-row argmin -> 8 ctile partials.
// score = |a|^2 - 2 q.a
// ---------------------------------------------------------------------------
__global__ __launch_bounds__(256)
void coarse_hmma() {
    extern __shared__ __align__(16) float dsm[];
    // A region: [s2][g4][f4][lane32][4] = 4096 floats. B: [s2][g4][nf16][lane32][2] = 8192.
    float* A_s = dsm;
    float* B_s = dsm + 4096;
    __shared__ float s_an[128];
    __shared__ float red_v[64][5];
    __shared__ int   red_i[64][5];

    const int qt = blockIdx.x, ct = blockIdx.y, b = blockIdx.z;
    const int q0 = qt * 64, c0 = ct * 128;
    const int tid  = threadIdx.x;
    const int wid  = tid >> 5;
    const int lane = tid & 31;
    const int warpM = wid >> 2;        // 0..1
    const int warpN = wid & 3;         // 0..3

    if (tid < 128) s_an[tid] = g_anorm[b * 1024 + c0 + tid];

    const size_t boff = (size_t)b * 1024 * 1024;
    const float* Aglob[2] = { g_qb + boff, g_qs2 + boff };
    const float* Bglob[2] = { g_cb + boff, g_cs2 + boff };

    float d[2][4][4];
#pragma unroll
    for (int mi = 0; mi < 2; mi++)
#pragma unroll
        for (int ni = 0; ni < 4; ni++)
#pragma unroll
            for (int e = 0; e < 4; e++) d[mi][ni][e] = 0.f;

    for (int ch = 0; ch < 32; ch++) {
        __syncthreads();
        // stage A: 2 splits x 64 rows x 8 float4  (1024 f4, 4 iters)
#pragma unroll
        for (int it = 0; it < 4; it++) {
            int i = tid + it * 256;
            int s   = i >> 9;
            int rem = i & 511;
            int row = rem >> 3;
            int kq  = rem & 7;
            float4 v = *(const float4*)(Aglob[s] + (size_t)(q0 + row) * 1024
                                        + ch * 32 + kq * 4);
            float vv[4] = { v.x, v.y, v.z, v.w };
            int f = row >> 4, rr = row & 15;
#pragma unroll
            for (int e4 = 0; e4 < 4; e4++) {
                int k = kq * 4 + e4;
                int g = k >> 3, kk = k & 7;
                int ln = (rr & 7) * 4 + (kk & 3);
                int el = (rr >> 3) + 2 * (kk >> 2);
                A_s[(((s * 4 + g) * 4 + f) * 32 + ln) * 4 + el] = vv[e4];
            }
        }
        // stage B: 2 splits x 128 rows x 8 float4  (2048 f4, 8 iters)
#pragma unroll
        for (int it = 0; it < 8; it++) {
            int i = tid + it * 256;
            int s   = i >> 10;
            int rem = i & 1023;
            int row = rem >> 3;
            int kq  = rem & 7;
            float4 v = *(const float4*)(Bglob[s] + (size_t)(c0 + row) * 1024
                                        + ch * 32 + kq * 4);
            float vv[4] = { v.x, v.y, v.z, v.w };
            int nf = row >> 3, nn = row & 7;
#pragma unroll
            for (int e4 = 0; e4 < 4; e4++) {
                int k = kq * 4 + e4;
                int g = k >> 3, kk = k & 7;
                int ln = nn * 4 + (kk & 3);
                int el = kk >> 2;
                B_s[(((s * 4 + g) * 16 + nf) * 32 + ln) * 2 + el] = vv[e4];
            }
        }
        __syncthreads();

        static const int PA[3] = {0, 0, 1};
        static const int PB[3] = {0, 1, 0};
#pragma unroll
        for (int g = 0; g < 4; g++) {
#pragma unroll
            for (int p = 0; p < 3; p++) {
                uint32_t afr[2][4];
#pragma unroll
                for (int mi = 0; mi < 2; mi++) {
                    const uint4 va = *(const uint4*)
                        &A_s[(((PA[p] * 4 + g) * 4 + (warpM * 2 + mi)) * 32 + lane) * 4];
                    afr[mi][0] = va.x; afr[mi][1] = va.y;
                    afr[mi][2] = va.z; afr[mi][3] = va.w;
                }
                uint32_t bfr[4][2];
#pragma unroll
                for (int ni = 0; ni < 4; ni++) {
                    const uint2 vb = *(const uint2*)
                        &B_s[(((PB[p] * 4 + g) * 16 + (warpN * 4 + ni)) * 32 + lane) * 2];
                    bfr[ni][0] = vb.x; bfr[ni][1] = vb.y;
                }
#pragma unroll
                for (int mi = 0; mi < 2; mi++)
#pragma unroll
                    for (int ni = 0; ni < 4; ni++)
                        mma_tf32(d[mi][ni], afr[mi], bfr[ni]);
            }
        }
    }
    __syncthreads();

    // epilogue: thread covers rows warpM*32 + mi*16 + ro*8 + lane/4,
    // cols warpN*32 + ni*8 + 2*(lane&3) + e; argmin in ascending col order.
#pragma unroll
    for (int mi = 0; mi < 2; mi++) {
#pragma unroll
        for (int ro = 0; ro < 2; ro++) {
            int rl = warpM * 32 + mi * 16 + ro * 8 + (lane >> 2);
            float bv = 3.402823466e38f; int bi = 0;
#pragma unroll
            for (int ni = 0; ni < 4; ni++) {
#pragma unroll
                for (int e = 0; e < 2; e++) {
                    int cl = warpN * 32 + ni * 8 + 2 * (lane & 3) + e;
                    int cand = c0 + cl;
                    float s = s_an[cl] - 2.f * d[mi][ni][ro * 2 + e];
                    if (s < bv || (s == bv && cand < bi)) { bv = s; bi = cand; }
                }
            }
#pragma unroll
            for (int off = 1; off < 4; off <<= 1) {
                float ov = __shfl_xor_sync(0xFFFFFFFFu, bv, off);
                int   oi = __shfl_xor_sync(0xFFFFFFFFu, bi, off);
                if (ov < bv || (ov == bv && oi < bi)) { bv = ov; bi = oi; }
            }
            if ((lane & 3) == 0) {
                red_v[rl][warpN] = bv;
                red_i[rl][warpN] = bi;
            }
        }
    }
    __syncthreads();
    if (tid < 64) {
        float bv = red_v[tid][0]; int bi = red_i[tid][0];
#pragma unroll
        for (int t = 1; t < 4; t++) {
            float v = red_v[tid][t]; int i2 = red_i[tid][t];
            if (v < bv || (v == bv && i2 < bi)) { bv = v; bi = i2; }
        }
        int q = b * 1024 + q0 + tid;
        g_pv[q * 8 + ct] = bv;
        g_pi[q * 8 + ct] = bi;
    }
}

// ---------------------------------------------------------------------------
// Kernel 2b: merge 8 ordered c-tile partials per query.
// ---------------------------------------------------------------------------
__global__ void merge_kernel(float* __restrict__ out) {
    int q = blockIdx.x * blockDim.x + threadIdx.x;
    if (q >= B_ * HC_ * WC_) return;
    float bv = g_pv[q * 8]; int bi = g_pi[q * 8];
#pragma unroll
    for (int s = 1; s < 8; s++) {
        float v = g_pv[q * 8 + s]; int i2 = g_pi[q * 8 + s];
        if (v < bv || (v == bv && i2 < bi)) { bv = v; bi = i2; }
    }
    int ro = bi >> 5, co = bi & 31;
    out[q * 2 + 0] = (float)ro;
    out[q * 2 + 1] = (float)co;
    g_cm[q * 2 + 0] = ro;
    g_cm[q * 2 + 1] = co;
}

// ---------------------------------------------------------------------------
// Kernel 3: fine match (R12, known-good). 4 cells/block, 8q x 8s f32x2.
// ---------------------------------------------------------------------------
__global__ __launch_bounds__(160, 4)
void fine_kernel(const float* __restrict__ F1,
                 const float* __restrict__ FK,
                 float* __restrict__ out) {
    const int b   = blockIdx.z;
    const int ci  = blockIdx.y;
    const int cj4 = blockIdx.x;
    const int tid = threadIdx.x;

    __shared__ __align__(16) unsigned char raw[37888 + 4096];
    typedef float CF[4][148];
    typedef float QF[4][16];
    CF* c_f = reinterpret_cast<CF*>(raw);
    QF* q_f = reinterpret_cast<QF*>(raw + 37888);
    float (*red_v)[16][20] = reinterpret_cast<float (*)[16][20]>(raw);
    int   (*red_i)[16][20] = reinterpret_cast<int   (*)[16][20]>(raw + 8192);
    __shared__ int nbr_r[4][9], nbr_c[4][9];

    if (tid < 36) {
        int cl = tid / 9, nb = tid % 9;
        int di = nb / 3 - 1, dj = nb % 3 - 1;
        int cjv = cj4 * 4 + cl;
        int ii = min(max(ci + di, 0), HC_ - 1);
        int jj = min(max(cjv + dj, 0), WC_ - 1);
        const int* p = g_cm + ((b * HC_ + ii) * WC_ + jj) * 2;
        nbr_r[cl][nb] = min(max(p[0], 0), HC_ - 1);
        nbr_c[cl][nb] = min(max(p[1], 0), WC_ - 1);
    }

    const float* F1b = F1 + (size_t)b * HF_ * WF_ * KF_;
    const float* fnb = g_fnorm + b * HF_ * WF_;

    const int ctid = (tid < 144) ? tid : 0;
    const int cell = ctid / 36;
    const int t36  = ctid % 36;
    const int qg   = t36 & 1;
    const int sg   = t36 >> 1;

    unsigned long long acc[8][4];
#pragma unroll
    for (int r = 0; r < 8; r++)
#pragma unroll
        for (int p = 0; p < 4; p++) acc[r][p] = 0ULL;

    for (int ksub = 0; ksub < 16; ksub++) {
        __syncthreads();
        for (int i = tid; i < 2304; i += 160) {
            int qtr = i / 576, row = i - qtr * 576;
            int cl = row / 144, sl = row - cl * 144;
            int n = sl >> 4, pp = sl & 15;
            int rr = nbr_r[cl][n] * DC_ + (pp >> 2);
            int cc = nbr_c[cl][n] * DC_ + (pp & 3);
            float4 v = *(const float4*)(F1b + (size_t)(rr * WF_ + cc) * KF_
                                        + ksub * 16 + qtr * 4);
            c_f[qtr * 4 + 0][cl][sl] = v.x;
            c_f[qtr * 4 + 1][cl][sl] = v.y;
            c_f[qtr * 4 + 2][cl][sl] = v.z;
            c_f[qtr * 4 + 3][cl][sl] = v.w;
        }
        for (int i = tid; i < 256; i += 160) {
            int cl = i >> 6, qp = (i >> 2) & 15, qtr = i & 3;
            int R = ci * DC_ + (qp >> 2);
            int C = (cj4 * 4 + cl) * DC_ + (qp & 3);
            float4 v = *(const float4*)(FK + ((size_t)(b * HF_ + R) * WF_ + C) * KF_
                                        + ksub * 16 + qtr * 4);
            q_f[qtr * 4 + 0][cl][qp] = v.x;
            q_f[qtr * 4 + 1][cl][qp] = v.y;
            q_f[qtr * 4 + 2][cl][qp] = v.z;
            q_f[qtr * 4 + 3][cl][qp] = v.w;
        }
        __syncthreads();
        if (tid < 144) {
#pragma unroll
            for (int k = 0; k < 16; k++) {
                float4 qa = *(const float4*)&q_f[k][cell][qg * 8];
                float4 qb = *(const float4*)&q_f[k][cell][qg * 8 + 4];
                ulonglong2 ca = *(const ulonglong2*)&c_f[k][cell][sg * 4];
                ulonglong2 cb = *(const ulonglong2*)&c_f[k][cell][72 + sg * 4];
                float qs[8] = { qa.x, qa.y, qa.z, qa.w, qb.x, qb.y, qb.z, qb.w };
#pragma unroll
                for (int r = 0; r < 8; r++) {
                    unsigned long long qd = dup2(qs[r]);
                    ffma2(acc[r][0], qd, ca.x);
                    ffma2(acc[r][1], qd, ca.y);
                    ffma2(acc[r][2], qd, cb.x);
                    ffma2(acc[r][3], qd, cb.y);
                }
            }
        }
    }

    __syncthreads();
    if (tid < 144) {
        float fn[8];
#pragma unroll
        for (int j = 0; j < 8; j++) {
            int slot = (j < 4) ? (sg * 4 + j) : (72 + sg * 4 + (j - 4));
            int n = slot >> 4, pp = slot & 15;
            int rr = nbr_r[cell][n] * DC_ + (pp >> 2);
            int cc = nbr_c[cell][n] * DC_ + (pp & 3);
            fn[j] = fnb[rr * WF_ + cc];
        }
#pragma unroll
        for (int r = 0; r < 8; r++) {
            float bv = 3.402823466e38f; int bi = 0;
#pragma unroll
            for (int p = 0; p < 4; p++) {
                F2U u; u.u = acc[r][p];
                int s0 = (p < 2) ? (sg * 4 + p * 2) : (72 + sg * 4 + (p - 2) * 2);
                int j0 = (p < 2) ? (p * 2) : (4 + (p - 2) * 2);
                float sc0 = fn[j0]     - 2.f * u.f.x;
                float sc1 = fn[j0 + 1] - 2.f * u.f.y;
                if (sc0 < bv || (sc0 == bv && s0 < bi))     { bv = sc0; bi = s0; }
                if (sc1 < bv || (sc1 == bv && s0 + 1 < bi)) { bv = sc1; bi = s0 + 1; }
            }
            red_v[cell][qg * 8 + r][sg] = bv;
            red_i[cell][qg * 8 + r][sg] = bi;
        }
    }
    __syncthreads();
    if (tid < 64) {
        int cl = tid >> 4, q = tid & 15;
        float bv = red_v[cl][q][0]; int bi = red_i[cl][q][0];
        for (int t = 1; t < 18; t++) {
            float v = red_v[cl][q][t]; int i2 = red_i[cl][q][t];
            if (v < bv || (v == bv && i2 < bi)) { bv = v; bi = i2; }
        }
        int n = bi >> 4, pp = bi & 15;
        int rr = nbr_r[cl][n] * DC_ + (pp >> 2);
        int cc = nbr_c[cl][n] * DC_ + (pp & 3);
        int R = ci * DC_ + (q >> 2);
        int C = (cj4 * 4 + cl) * DC_ + (q & 3);
        float* o = out + ((size_t)(b * HF_ + R) * WF_ + C) * 2;
        o[0] = (float)rr; o[1] = (float)cc;
    }
}

// ---------------------------------------------------------------------------
extern "C" void kernel_launch(void* const* d_in, const int* in_sizes, int n_in,
                              void* d_out, int out_size) {
    int idx[16];
    int m = n_in < 16 ? n_in : 16;
    for (int i = 0; i < m; i++) idx[i] = i;
    for (int i = 1; i < m; i++) {
        int key = idx[i];
        long long ks = in_sizes[key];
        int j = i - 1;
        while (j >= 0 && (long long)in_sizes[idx[j]] > ks) {
            idx[j + 1] = idx[j]; j--;
        }
        idx[j + 1] = key;
    }
    if (m < 4) return;
    const float* g1c = (const float*)d_in[idx[0]];      // F_g1_coarse
    const float* gkc = (const float*)d_in[idx[1]];      // F_gk_coarse
    const float* g1f = (const float*)d_in[idx[m - 2]];  // F_g1_fine
    const float* gkf = (const float*)d_in[idx[m - 1]];  // F_gk_fine
    float* out = (float*)d_out;

    const int DSM = (4096 + 8192) * 4;   // 48 KB fragment-major staging
    cudaFuncSetAttribute(coarse_hmma, cudaFuncAttributeMaxDynamicSharedMemorySize, DSM);

    norms_kernel<<<(B_ * HC_ * WC_ + B_ * HF_ * WF_) / 8, 256>>>(g1c, g1f);
    convert_kernel<<<8192 / 8, 256>>>(g1c, gkc);

    dim3 gc(16, 8, B_);
    coarse_hmma<<<gc, 256, DSM>>>();

    merge_kernel<<<(B_ * HC_ * WC_ + 255) / 256, 256>>>(out);

    dim3 gf(WC_ / 4, HC_, B_);
    fine_kernel<<<gf, 160>>>(g1f, gkf, out + B_ * HC_ * WC_ * 2);
}

// round 17
// speedup vs baseline: 1.0591x; 1.0032x over previous
#include <cuda_runtime.h>
#include <cstdint>

#define B_  4
#define HC_ 32
#define WC_ 32
#define KC_ 1024
#define HF_ 128
#define WF_ 128
#define KF_ 256
#define DC_ 4

__device__ float g_anorm[B_ * HC_ * WC_];
__device__ float g_fnorm[B_ * HF_ * WF_];
__device__ int   g_cm[B_ * HC_ * WC_ * 2];
__device__ float g_pv[B_ * 1024 * 8];     // [q][ctile]
__device__ int   g_pi[B_ * 1024 * 8];
// 3xTF32 splits (fp32 bit-exact tf32 values): [b][row][k]
__device__ float g_qb[(size_t)B_ * 1024 * 1024];
__device__ float g_qs2[(size_t)B_ * 1024 * 1024];
__device__ float g_cb[(size_t)B_ * 1024 * 1024];
__device__ float g_cs2[(size_t)B_ * 1024 * 1024];

union F2U { unsigned long long u; float2 f; };

__device__ __forceinline__ void ffma2(unsigned long long &d,
                                      unsigned long long a,
                                      unsigned long long b) {
    asm("fma.rn.f32x2 %0, %1, %2, %0;" : "+l"(d) : "l"(a), "l"(b));
}
__device__ __forceinline__ unsigned long long dup2(float x) {
    unsigned long long r;
    asm("mov.b64 %0, {%1, %1};" : "=l"(r) : "f"(x));
    return r;
}
__device__ __forceinline__ uint32_t tf32_of(float x) {
    uint32_t r;
    asm("cvt.rna.tf32.f32 %0, %1;" : "=r"(r) : "f"(x));
    return r;
}
__device__ __forceinline__ void mma_tf32(float* d, const uint32_t* a,
                                         const uint32_t* b) {
    asm volatile(
        "mma.sync.aligned.m16n8k8.row.col.f32.tf32.tf32.f32 "
        "{%0,%1,%2,%3}, {%4,%5,%6,%7}, {%8,%9}, {%0,%1,%2,%3};"
        : "+f"(d[0]), "+f"(d[1]), "+f"(d[2]), "+f"(d[3])
        : "r"(a[0]), "r"(a[1]), "r"(a[2]), "r"(a[3]), "r"(b[0]), "r"(b[1]));
}

// ---------------------------------------------------------------------------
// Kernel 1: FINE candidate squared norms only (coarse norms fused into
// convert_kernel). One warp per row, DRAM-bound.
// ---------------------------------------------------------------------------
__global__ void norms_fine_kernel(const float* __restrict__ g1f) {
    int r    = (blockIdx.x * blockDim.x + threadIdx.x) >> 5;
    int lane = threadIdx.x & 31;
    if (r >= B_ * HF_ * WF_) return;
    const float* p = g1f + (size_t)r * KF_;
    float s = 0.f;
#pragma unroll
    for (int i = 0; i < KF_ / 32; i++) { float v = p[lane + i * 32]; s += v * v; }
#pragma unroll
    for (int o = 16; o; o >>= 1) s += __shfl_xor_sync(0xFFFFFFFFu, s, o);
    if (lane == 0) g_fnorm[r] = s;
}

// ---------------------------------------------------------------------------
// Kernel 1b: 3xTF32 split of coarse tensors + fused coarse candidate norms.
// One warp per row (8192 rows: first 4096 = g1c/candidates, rest = gkc).
// ---------------------------------------------------------------------------
__global__ void convert_kernel(const float* __restrict__ g1c,
                               const float* __restrict__ gkc) {
    int row  = blockIdx.x * 8 + (threadIdx.x >> 5);
    int lane = threadIdx.x & 31;
    int r = row & 4095;
    bool is_c = (row < 4096);
    const float* src = (is_c ? g1c : gkc) + (size_t)r * 1024;
    float* db = (is_c ? g_cb : g_qb)  + (size_t)r * 1024;
    float* ds = (is_c ? g_cs2 : g_qs2) + (size_t)r * 1024;
    float nrm = 0.f;
    for (int i = lane; i < 1024; i += 32) {
        float x = src[i];
        uint32_t bb = tf32_of(x);
        float bf = __uint_as_float(bb);
        uint32_t sb = tf32_of(x - bf);
        db[i] = bf;
        ds[i] = __uint_as_float(sb);
        nrm += x * x;
    }
    if (is_c) {
#pragma unroll
        for (int o = 16; o; o >>= 1) nrm += __shfl_xor_sync(0xFFFFFFFFu, nrm, o);
        if (lane == 0) g_anorm[r] = nrm;
    }
}

// ---------------------------------------------------------------------------
// Kernel 2: coarse match on mma.sync (tf32, 3xTF32). Validated layouts (R14).
// Change vs R14: per k8-group, A/B fragments of BOTH splits are loaded once
// into registers; the three products (bb, bs, sb) reuse them in the SAME
// accumulation order (bit-identical results, fewer LDS wavefronts).
// ---------------------------------------------------------------------------
__global__ __launch_bounds__(256)
void coarse_hmma() {
    extern __shared__ __align__(16) float dsm[];
    float* A_s = dsm;
    float* B_s = dsm + 4096;
    __shared__ float s_an[128];
    __shared__ float red_v[64][5];
    __shared__ int   red_i[64][5];

    const int qt = blockIdx.x, ct = blockIdx.y, b = blockIdx.z;
    const int q0 = qt * 64, c0 = ct * 128;
    const int tid  = threadIdx.x;
    const int wid  = tid >> 5;
    const int lane = tid & 31;
    const int warpM = wid >> 2;
    const int warpN = wid & 3;

    if (tid < 128) s_an[tid] = g_anorm[b * 1024 + c0 + tid];

    const size_t boff = (size_t)b * 1024 * 1024;
    const float* Aglob[2] = { g_qb + boff, g_qs2 + boff };
    const float* Bglob[2] = { g_cb + boff, g_cs2 + boff };

    float d[2][4][4];
#pragma unroll
    for (int mi = 0; mi < 2; mi++)
#pragma unroll
        for (int ni = 0; ni < 4; ni++)
#pragma unroll
            for (int e = 0; e < 4; e++) d[mi][ni][e] = 0.f;

    for (int ch = 0; ch < 32; ch++) {
        __syncthreads();
#pragma unroll
        for (int it = 0; it < 4; it++) {
            int i = tid + it * 256;
            int s = i >> 9, rem = i & 511;
            int row = rem >> 3, kq = rem & 7;
            float4 v = *(const float4*)(Aglob[s] + (size_t)(q0 + row) * 1024
                                        + ch * 32 + kq * 4);
            float vv[4] = { v.x, v.y, v.z, v.w };
            int f = row >> 4, rr = row & 15;
#pragma unroll
            for (int e4 = 0; e4 < 4; e4++) {
                int k = kq * 4 + e4;
                int g = k >> 3, kk = k & 7;
                int ln = (rr & 7) * 4 + (kk & 3);
                int el = (rr >> 3) + 2 * (kk >> 2);
                A_s[(((s * 4 + g) * 4 + f) * 32 + ln) * 4 + el] = vv[e4];
            }
        }
#pragma unroll
        for (int it = 0; it < 8; it++) {
            int i = tid + it * 256;
            int s = i >> 10, rem = i & 1023;
            int row = rem >> 3, kq = rem & 7;
            float4 v = *(const float4*)(Bglob[s] + (size_t)(c0 + row) * 1024
                                        + ch * 32 + kq * 4);
            float vv[4] = { v.x, v.y, v.z, v.w };
            int nf = row >> 3, nn = row & 7;
#pragma unroll
            for (int e4 = 0; e4 < 4; e4++) {
                int k = kq * 4 + e4;
                int g = k >> 3, kk = k & 7;
                int ln = nn * 4 + (kk & 3);
                int el = kk >> 2;
                B_s[(((s * 4 + g) * 16 + nf) * 32 + ln) * 2 + el] = vv[e4];
            }
        }
        __syncthreads();

        static const int PA[3] = {0, 0, 1};
        static const int PB[3] = {0, 1, 0};
#pragma unroll
        for (int g = 0; g < 4; g++) {
            // hoisted loads: both splits of A (2x2 frags) and B (2x4 frags)
            uint32_t afr[2][2][4];
#pragma unroll
            for (int s = 0; s < 2; s++)
#pragma unroll
                for (int mi = 0; mi < 2; mi++) {
                    const uint4 va = *(const uint4*)
                        &A_s[(((s * 4 + g) * 4 + (warpM * 2 + mi)) * 32 + lane) * 4];
                    afr[s][mi][0] = va.x; afr[s][mi][1] = va.y;
                    afr[s][mi][2] = va.z; afr[s][mi][3] = va.w;
                }
            uint32_t bfr[2][4][2];
#pragma unroll
            for (int s = 0; s < 2; s++)
#pragma unroll
                for (int ni = 0; ni < 4; ni++) {
                    const uint2 vb = *(const uint2*)
                        &B_s[(((s * 4 + g) * 16 + (warpN * 4 + ni)) * 32 + lane) * 2];
                    bfr[s][ni][0] = vb.x; bfr[s][ni][1] = vb.y;
                }
            // same accumulation order as R14: p = bb, bs, sb
#pragma unroll
            for (int p = 0; p < 3; p++)
#pragma unroll
                for (int mi = 0; mi < 2; mi++)
#pragma unroll
                    for (int ni = 0; ni < 4; ni++)
                        mma_tf32(d[mi][ni], afr[PA[p]][mi], bfr[PB[p]][ni]);
        }
    }
    __syncthreads();

#pragma unroll
    for (int mi = 0; mi < 2; mi++) {
#pragma unroll
        for (int ro = 0; ro < 2; ro++) {
            int rl = warpM * 32 + mi * 16 + ro * 8 + (lane >> 2);
            float bv = 3.402823466e38f; int bi = 0;
#pragma unroll
            for (int ni = 0; ni < 4; ni++) {
#pragma unroll
                for (int e = 0; e < 2; e++) {
                    int cl = warpN * 32 + ni * 8 + 2 * (lane & 3) + e;
                    int cand = c0 + cl;
                    float s = s_an[cl] - 2.f * d[mi][ni][ro * 2 + e];
                    if (s < bv || (s == bv && cand < bi)) { bv = s; bi = cand; }
                }
            }
#pragma unroll
            for (int off = 1; off < 4; off <<= 1) {
                float ov = __shfl_xor_sync(0xFFFFFFFFu, bv, off);
                int   oi = __shfl_xor_sync(0xFFFFFFFFu, bi, off);
                if (ov < bv || (ov == bv && oi < bi)) { bv = ov; bi = oi; }
            }
            if ((lane & 3) == 0) {
                red_v[rl][warpN] = bv;
                red_i[rl][warpN] = bi;
            }
        }
    }
    __syncthreads();
    if (tid < 64) {
        float bv = red_v[tid][0]; int bi = red_i[tid][0];
#pragma unroll
        for (int t = 1; t < 4; t++) {
            float v = red_v[tid][t]; int i2 = red_i[tid][t];
            if (v < bv || (v == bv && i2 < bi)) { bv = v; bi = i2; }
        }
        int q = b * 1024 + q0 + tid;
        g_pv[q * 8 + ct] = bv;
        g_pi[q * 8 + ct] = bi;
    }
}

// ---------------------------------------------------------------------------
// Kernel 2b: merge 8 ordered c-tile partials per query.
// ---------------------------------------------------------------------------
__global__ void merge_kernel(float* __restrict__ out) {
    int q = blockIdx.x * blockDim.x + threadIdx.x;
    if (q >= B_ * HC_ * WC_) return;
    float bv = g_pv[q * 8]; int bi = g_pi[q * 8];
#pragma unroll
    for (int s = 1; s < 8; s++) {
        float v = g_pv[q * 8 + s]; int i2 = g_pi[q * 8 + s];
        if (v < bv || (v == bv && i2 < bi)) { bv = v; bi = i2; }
    }
    int ro = bi >> 5, co = bi & 31;
    out[q * 2 + 0] = (float)ro;
    out[q * 2 + 1] = (float)co;
    g_cm[q * 2 + 0] = ro;
    g_cm[q * 2 + 1] = co;
}

// ---------------------------------------------------------------------------
// Kernel 3: fine match (R12, known-good, passed twice). 4 cells/block,
// 160 thr, 8q x 8s f32x2 register tiles.
// ---------------------------------------------------------------------------
__global__ __launch_bounds__(160, 4)
void fine_kernel(const float* __restrict__ F1,
                 const float* __restrict__ FK,
                 float* __restrict__ out) {
    const int b   = blockIdx.z;
    const int ci  = blockIdx.y;
    const int cj4 = blockIdx.x;
    const int tid = threadIdx.x;

    __shared__ __align__(16) unsigned char raw[37888 + 4096];
    typedef float CF[4][148];
    typedef float QF[4][16];
    CF* c_f = reinterpret_cast<CF*>(raw);
    QF* q_f = reinterpret_cast<QF*>(raw + 37888);
    float (*red_v)[16][20] = reinterpret_cast<float (*)[16][20]>(raw);
    int   (*red_i)[16][20] = reinterpret_cast<int   (*)[16][20]>(raw + 8192);
    __shared__ int nbr_r[4][9], nbr_c[4][9];

    if (tid < 36) {
        int cl = tid / 9, nb = tid % 9;
        int di = nb / 3 - 1, dj = nb % 3 - 1;
        int cjv = cj4 * 4 + cl;
        int ii = min(max(ci + di, 0), HC_ - 1);
        int jj = min(max(cjv + dj, 0), WC_ - 1);
        const int* p = g_cm + ((b * HC_ + ii) * WC_ + jj) * 2;
        nbr_r[cl][nb] = min(max(p[0], 0), HC_ - 1);
        nbr_c[cl][nb] = min(max(p[1], 0), WC_ - 1);
    }

    const float* F1b = F1 + (size_t)b * HF_ * WF_ * KF_;
    const float* fnb = g_fnorm + b * HF_ * WF_;

    const int ctid = (tid < 144) ? tid : 0;
    const int cell = ctid / 36;
    const int t36  = ctid % 36;
    const int qg   = t36 & 1;
    const int sg   = t36 >> 1;

    unsigned long long acc[8][4];
#pragma unroll
    for (int r = 0; r < 8; r++)
#pragma unroll
        for (int p = 0; p < 4; p++) acc[r][p] = 0ULL;

    for (int ksub = 0; ksub < 16; ksub++) {
        __syncthreads();
        for (int i = tid; i < 2304; i += 160) {
            int qtr = i / 576, row = i - qtr * 576;
            int cl = row / 144, sl = row - cl * 144;
            int n = sl >> 4, pp = sl & 15;
            int rr = nbr_r[cl][n] * DC_ + (pp >> 2);
            int cc = nbr_c[cl][n] * DC_ + (pp & 3);
            float4 v = *(const float4*)(F1b + (size_t)(rr * WF_ + cc) * KF_
                                        + ksub * 16 + qtr * 4);
            c_f[qtr * 4 + 0][cl][sl] = v.x;
            c_f[qtr * 4 + 1][cl][sl] = v.y;
            c_f[qtr * 4 + 2][cl][sl] = v.z;
            c_f[qtr * 4 + 3][cl][sl] = v.w;
        }
        for (int i = tid; i < 256; i += 160) {
            int cl = i >> 6, qp = (i >> 2) & 15, qtr = i & 3;
            int R = ci * DC_ + (qp >> 2);
            int C = (cj4 * 4 + cl) * DC_ + (qp & 3);
            float4 v = *(const float4*)(FK + ((size_t)(b * HF_ + R) * WF_ + C) * KF_
                                        + ksub * 16 + qtr * 4);
            q_f[qtr * 4 + 0][cl][qp] = v.x;
            q_f[qtr * 4 + 1][cl][qp] = v.y;
            q_f[qtr * 4 + 2][cl][qp] = v.z;
            q_f[qtr * 4 + 3][cl][qp] = v.w;
        }
        __syncthreads();
        if (tid < 144) {
#pragma unroll
            for (int k = 0; k < 16; k++) {
                float4 qa = *(const float4*)&q_f[k][cell][qg * 8];
                float4 qb = *(const float4*)&q_f[k][cell][qg * 8 + 4];
                ulonglong2 ca = *(const ulonglong2*)&c_f[k][cell][sg * 4];
                ulonglong2 cb = *(const ulonglong2*)&c_f[k][cell][72 + sg * 4];
                float qs[8] = { qa.x, qa.y, qa.z, qa.w, qb.x, qb.y, qb.z, qb.w };
#pragma unroll
                for (int r = 0; r < 8; r++) {
                    unsigned long long qd = dup2(qs[r]);
                    ffma2(acc[r][0], qd, ca.x);
                    ffma2(acc[r][1], qd, ca.y);
                    ffma2(acc[r][2], qd, cb.x);
                    ffma2(acc[r][3], qd, cb.y);
                }
            }
        }
    }

    __syncthreads();
    if (tid < 144) {
        float fn[8];
#pragma unroll
        for (int j = 0; j < 8; j++) {
            int slot = (j < 4) ? (sg * 4 + j) : (72 + sg * 4 + (j - 4));
            int n = slot >> 4, pp = slot & 15;
            int rr = nbr_r[cell][n] * DC_ + (pp >> 2);
            int cc = nbr_c[cell][n] * DC_ + (pp & 3);
            fn[j] = fnb[rr * WF_ + cc];
        }
#pragma unroll
        for (int r = 0; r < 8; r++) {
            float bv = 3.402823466e38f; int bi = 0;
#pragma unroll
            for (int p = 0; p < 4; p++) {
                F2U u; u.u = acc[r][p];
                int s0 = (p < 2) ? (sg * 4 + p * 2) : (72 + sg * 4 + (p - 2) * 2);
                int j0 = (p < 2) ? (p * 2) : (4 + (p - 2) * 2);
                float sc0 = fn[j0]     - 2.f * u.f.x;
                float sc1 = fn[j0 + 1] - 2.f * u.f.y;
                if (sc0 < bv || (sc0 == bv && s0 < bi))     { bv = sc0; bi = s0; }
                if (sc1 < bv || (sc1 == bv && s0 + 1 < bi)) { bv = sc1; bi = s0 + 1; }
            }
            red_v[cell][qg * 8 + r][sg] = bv;
            red_i[cell][qg * 8 + r][sg] = bi;
        }
    }
    __syncthreads();
    if (tid < 64) {
        int cl = tid >> 4, q = tid & 15;
        float bv = red_v[cl][q][0]; int bi = red_i[cl][q][0];
        for (int t = 1; t < 18; t++) {
            float v = red_v[cl][q][t]; int i2 = red_i[cl][q][t];
            if (v < bv || (v == bv && i2 < bi)) { bv = v; bi = i2; }
        }
        int n = bi >> 4, pp = bi & 15;
        int rr = nbr_r[cl][n] * DC_ + (pp >> 2);
        int cc = nbr_c[cl][n] * DC_ + (pp & 3);
        int R = ci * DC_ + (q >> 2);
        int C = (cj4 * 4 + cl) * DC_ + (q & 3);
        float* o = out + ((size_t)(b * HF_ + R) * WF_ + C) * 2;
        o[0] = (float)rr; o[1] = (float)cc;
    }
}

// ---------------------------------------------------------------------------
extern "C" void kernel_launch(void* const* d_in, const int* in_sizes, int n_in,
                              void* d_out, int out_size) {
    int idx[16];
    int m = n_in < 16 ? n_in : 16;
    for (int i = 0; i < m; i++) idx[i] = i;
    for (int i = 1; i < m; i++) {
        int key = idx[i];
        long long ks = in_sizes[key];
        int j = i - 1;
        while (j >= 0 && (long long)in_sizes[idx[j]] > ks) {
            idx[j + 1] = idx[j]; j--;
        }
        idx[j + 1] = key;
    }
    if (m < 4) return;
    const float* g1c = (const float*)d_in[idx[0]];      // F_g1_coarse
    const float* gkc = (const float*)d_in[idx[1]];      // F_gk_coarse
    const float* g1f = (const float*)d_in[idx[m - 2]];  // F_g1_fine
    const float* gkf = (const float*)d_in[idx[m - 1]];  // F_gk_fine
    float* out = (float*)d_out;

    const int DSM_C = (4096 + 8192) * 4;   // 48 KB
    cudaFuncSetAttribute(coarse_hmma, cudaFuncAttributeMaxDynamicSharedMemorySize, DSM_C);

    convert_kernel<<<8192 / 8, 256>>>(g1c, gkc);
    norms_fine_kernel<<<(B_ * HF_ * WF_) / 8, 256>>>(g1f);

    dim3 gc(16, 8, B_);
    coarse_hmma<<<gc, 256, DSM_C>>>();

    merge_kernel<<<(B_ * HC_ * WC_ + 255) / 256, 256>>>(out);

    dim3 gf(WC_ / 4, HC_, B_);
    fine_kernel<<<gf, 160>>>(g1f, gkf, out + B_ * HC_ * WC_ * 2);
}